// round 1
// baseline (speedup 1.0000x reference)
#include <cuda_runtime.h>
#include <math.h>

#define BB 8
#define SS 2048
#define DD 768
#define HH 3072
#define NROWS (BB*SS)   // 16384

// ---------------- scratch (device globals: no allocations allowed) ----------
__device__ float g_h [NROWS*DD];            // ln1 out
__device__ float g_q [NROWS*DD];
__device__ float g_k [NROWS*DD];
__device__ float g_v [NROWS*DD];
__device__ float g_s [(size_t)BB*SS*SS];    // scores / attn probs (128 MB)
__device__ float g_y [NROWS*DD];            // attn @ V
__device__ float g_x1[NROWS*DD];            // after attn residual
__device__ float g_h2[NROWS*DD];            // ln2 out
__device__ float g_m [(size_t)NROWS*HH];    // gelu(fc) (201 MB)

// ---------------- LayerNorm: one block per row of 768 -----------------------
__global__ void ln_kernel(const float* __restrict__ x, const float* __restrict__ gw,
                          const float* __restrict__ bw, float* __restrict__ out) {
    size_t base = (size_t)blockIdx.x * DD;
    int tid = threadIdx.x;  // 256
    float v0 = x[base+tid], v1 = x[base+tid+256], v2 = x[base+tid+512];
    float s  = v0+v1+v2;
    float sq = v0*v0 + v1*v1 + v2*v2;
    #pragma unroll
    for (int o = 16; o; o >>= 1) {
        s  += __shfl_xor_sync(0xffffffffu, s,  o);
        sq += __shfl_xor_sync(0xffffffffu, sq, o);
    }
    __shared__ float rs[8], rq[8];
    __shared__ float mu_s, rstd_s;
    int w = tid >> 5;
    if ((tid & 31) == 0) { rs[w] = s; rq[w] = sq; }
    __syncthreads();
    if (tid == 0) {
        float a = 0.f, c = 0.f;
        #pragma unroll
        for (int i = 0; i < 8; i++) { a += rs[i]; c += rq[i]; }
        float mu  = a * (1.f/DD);
        float var = c * (1.f/DD) - mu*mu;
        mu_s = mu; rstd_s = rsqrtf(var + 1e-5f);
    }
    __syncthreads();
    float mu = mu_s, r = rstd_s;
    out[base+tid]     = (v0-mu)*r*gw[tid]     + bw[tid];
    out[base+tid+256] = (v1-mu)*r*gw[tid+256] + bw[tid+256];
    out[base+tid+512] = (v2-mu)*r*gw[tid+512] + bw[tid+512];
}

// ---------------- softmax over last dim (2048), one block per row ------------
__global__ void softmax_kernel(float* __restrict__ sc) {
    size_t base = (size_t)blockIdx.x * SS;
    int tid = threadIdx.x;  // 256
    float v[8];
    float mx = -1e30f;
    #pragma unroll
    for (int i = 0; i < 8; i++) { v[i] = sc[base + tid + i*256]; mx = fmaxf(mx, v[i]); }
    #pragma unroll
    for (int o = 16; o; o >>= 1) mx = fmaxf(mx, __shfl_xor_sync(0xffffffffu, mx, o));
    __shared__ float rm[8];
    __shared__ float bmax, binv;
    int w = tid >> 5;
    if ((tid & 31) == 0) rm[w] = mx;
    __syncthreads();
    if (tid == 0) {
        float m2 = rm[0];
        #pragma unroll
        for (int i = 1; i < 8; i++) m2 = fmaxf(m2, rm[i]);
        bmax = m2;
    }
    __syncthreads();
    mx = bmax;
    float s = 0.f;
    #pragma unroll
    for (int i = 0; i < 8; i++) { v[i] = expf(v[i] - mx); s += v[i]; }
    #pragma unroll
    for (int o = 16; o; o >>= 1) s += __shfl_xor_sync(0xffffffffu, s, o);
    if ((tid & 31) == 0) rm[w] = s;
    __syncthreads();
    if (tid == 0) {
        float t = 0.f;
        #pragma unroll
        for (int i = 0; i < 8; i++) t += rm[i];
        binv = 1.f / t;
    }
    __syncthreads();
    float inv = binv;
    #pragma unroll
    for (int i = 0; i < 8; i++) sc[base + tid + i*256] = v[i] * inv;
}

// ---------------- SGEMM 128x128x16, 8x8 microtile, 256 threads ---------------
// C[M,N] = epi( alpha * A[M,K] @ op(B) + bias (+ res) )
// TRANSB=false: B is [K,N] row-major.  TRANSB=true: B is [N,K] row-major (NT).
// EPI: 0 = alpha only, 1 = +bias, 2 = +bias then exact GELU, 3 = +bias +res
template <bool TRANSB, int EPI>
__global__ __launch_bounds__(256, 2)
void gemm_kernel(const float* __restrict__ A, const float* __restrict__ B,
                 const float* __restrict__ bias, const float* __restrict__ res,
                 float* __restrict__ C,
                 int M, int N, int K, float alpha,
                 size_t sA, size_t sB, size_t sC)
{
    A += (size_t)blockIdx.z * sA;
    B += (size_t)blockIdx.z * sB;
    C += (size_t)blockIdx.z * sC;

    __shared__ float As[16][128];
    __shared__ float Bs[16][128];

    int tid = threadIdx.x;
    int m0 = blockIdx.y * 128;
    int n0 = blockIdx.x * 128;

    int tx = tid & 15;   // n micro-tile
    int ty = tid >> 4;   // m micro-tile

    // loader indices
    int ar = tid >> 2;          // 0..63 (row within half-tile)
    int ac = (tid & 3) * 4;     // 0,4,8,12 (k within BK)
    int br = tid >> 5;          // 0..7   (k row for NN B load)
    int bc = (tid & 31) * 4;    // 0..124 (n col for NN B load)

    float acc[8][8];
    #pragma unroll
    for (int i = 0; i < 8; i++)
        #pragma unroll
        for (int j = 0; j < 8; j++) acc[i][j] = 0.f;

    for (int k0 = 0; k0 < K; k0 += 16) {
        // load A tile, transposed into As[k][m]
        #pragma unroll
        for (int p = 0; p < 2; p++) {
            int m = ar + p*64;
            float4 va = *(const float4*)(A + (size_t)(m0+m)*K + k0 + ac);
            As[ac+0][m] = va.x; As[ac+1][m] = va.y;
            As[ac+2][m] = va.z; As[ac+3][m] = va.w;
        }
        if (!TRANSB) {
            #pragma unroll
            for (int p = 0; p < 2; p++) {
                int kk = br + p*8;
                float4 vb = *(const float4*)(B + (size_t)(k0+kk)*N + n0 + bc);
                *(float4*)(&Bs[kk][bc]) = vb;
            }
        } else {
            #pragma unroll
            for (int p = 0; p < 2; p++) {
                int n = ar + p*64;
                float4 vb = *(const float4*)(B + (size_t)(n0+n)*K + k0 + ac);
                Bs[ac+0][n] = vb.x; Bs[ac+1][n] = vb.y;
                Bs[ac+2][n] = vb.z; Bs[ac+3][n] = vb.w;
            }
        }
        __syncthreads();

        #pragma unroll
        for (int kk = 0; kk < 16; kk++) {
            float a[8], bf[8];
            #pragma unroll
            for (int i = 0; i < 8; i++) a[i]  = As[kk][ty*8 + i];
            #pragma unroll
            for (int j = 0; j < 8; j++) bf[j] = Bs[kk][tx*8 + j];
            #pragma unroll
            for (int i = 0; i < 8; i++)
                #pragma unroll
                for (int j = 0; j < 8; j++)
                    acc[i][j] += a[i] * bf[j];
        }
        __syncthreads();
    }

    // epilogue
    #pragma unroll
    for (int i = 0; i < 8; i++) {
        size_t m = (size_t)m0 + ty*8 + i;
        #pragma unroll
        for (int j = 0; j < 8; j++) {
            int n = n0 + tx*8 + j;
            float vv = acc[i][j] * alpha;
            if (EPI >= 1) vv += bias[n];
            if (EPI == 2) vv = 0.5f * vv * (1.f + erff(vv * 0.70710678118654752f));
            if (EPI == 3) vv += res[m * N + n];
            C[m * N + n] = vv;
        }
    }
}

// ---------------- host ------------------------------------------------------
static float* sym_addr(const void* s) {
    void* p = nullptr;
    cudaGetSymbolAddress(&p, s);   // address query only; capture-safe, no alloc
    return (float*)p;
}

extern "C" void kernel_launch(void* const* d_in, const int* in_sizes, int n_in,
                              void* d_out, int out_size) {
    const float* x     = (const float*)d_in[0];
    const float* ln1_g = (const float*)d_in[1];
    const float* ln1_b = (const float*)d_in[2];
    const float* ln2_g = (const float*)d_in[3];
    const float* ln2_b = (const float*)d_in[4];
    const float* Wq    = (const float*)d_in[5];
    const float* bq    = (const float*)d_in[6];
    const float* Wk    = (const float*)d_in[7];
    const float* bk    = (const float*)d_in[8];
    const float* Wv    = (const float*)d_in[9];
    const float* bv    = (const float*)d_in[10];
    const float* Wo    = (const float*)d_in[11];
    const float* bo    = (const float*)d_in[12];
    const float* Wfc   = (const float*)d_in[13];
    const float* bfc   = (const float*)d_in[14];
    const float* Wproj = (const float*)d_in[15];
    const float* bproj = (const float*)d_in[16];
    float* out = (float*)d_out;

    float* h  = sym_addr(g_h);
    float* q  = sym_addr(g_q);
    float* k  = sym_addr(g_k);
    float* v  = sym_addr(g_v);
    float* s  = sym_addr(g_s);
    float* y  = sym_addr(g_y);
    float* x1 = sym_addr(g_x1);
    float* h2 = sym_addr(g_h2);
    float* m  = sym_addr(g_m);

    const float inv_sqrt_d = 1.0f / sqrtf((float)DD);

    // 1) ln1
    ln_kernel<<<NROWS, 256>>>(x, ln1_g, ln1_b, h);

    // 2) q, k, v = h @ W + b    [16384,768] @ [768,768]
    dim3 gqkv(DD/128, NROWS/128, 1);
    gemm_kernel<false,1><<<gqkv, 256>>>(h, Wq, bq, nullptr, q, NROWS, DD, DD, 1.f, 0, 0, 0);
    gemm_kernel<false,1><<<gqkv, 256>>>(h, Wk, bk, nullptr, k, NROWS, DD, DD, 1.f, 0, 0, 0);
    gemm_kernel<false,1><<<gqkv, 256>>>(h, Wv, bv, nullptr, v, NROWS, DD, DD, 1.f, 0, 0, 0);

    // 3) scores = (q @ k^T) / sqrt(D), batched over B     [2048,768]x[2048,768]^T
    dim3 gsc(SS/128, SS/128, BB);
    gemm_kernel<true,0><<<gsc, 256>>>(q, k, nullptr, nullptr, s,
                                      SS, SS, DD, inv_sqrt_d,
                                      (size_t)SS*DD, (size_t)SS*DD, (size_t)SS*SS);

    // 4) softmax over keys
    softmax_kernel<<<NROWS, 256>>>(s);

    // 5) y = attn @ v, batched    [2048,2048] @ [2048,768]
    dim3 gav(DD/128, SS/128, BB);
    gemm_kernel<false,0><<<gav, 256>>>(s, v, nullptr, nullptr, y,
                                       SS, DD, SS, 1.f,
                                       (size_t)SS*SS, (size_t)SS*DD, (size_t)SS*DD);

    // 6) x1 = x + y @ Wo + bo
    gemm_kernel<false,3><<<gqkv, 256>>>(y, Wo, bo, x, x1, NROWS, DD, DD, 1.f, 0, 0, 0);

    // 7) ln2
    ln_kernel<<<NROWS, 256>>>(x1, ln2_g, ln2_b, h2);

    // 8) m = gelu(h2 @ Wfc + bfc)   [16384,768] @ [768,3072]
    dim3 gfc(HH/128, NROWS/128, 1);
    gemm_kernel<false,2><<<gfc, 256>>>(h2, Wfc, bfc, nullptr, m, NROWS, HH, DD, 1.f, 0, 0, 0);

    // 9) out = x1 + m @ Wproj + bproj   [16384,3072] @ [3072,768]
    gemm_kernel<false,3><<<gqkv, 256>>>(m, Wproj, bproj, x1, out, NROWS, DD, HH, 1.f, 0, 0, 0);
}

// round 13
// speedup vs baseline: 2.6023x; 2.6023x over previous
#include <cuda_runtime.h>
#include <cstdint>
#include <math.h>

#define BB 8
#define SS 2048
#define DD 768
#define HH 3072
#define NROWS (BB*SS)   // 16384

// ---------------- scratch (device globals: no allocations allowed) ----------
__device__ float g_h [NROWS*DD];
__device__ float g_q [NROWS*DD];
__device__ float g_k [NROWS*DD];
__device__ float g_v [NROWS*DD];
__device__ float g_vt[(size_t)BB*DD*SS];
__device__ float g_s [(size_t)BB*SS*SS];
__device__ float g_y [NROWS*DD];
__device__ float g_x1[NROWS*DD];
__device__ float g_h2[NROWS*DD];
__device__ float g_m [(size_t)NROWS*HH];
__device__ float g_wqt[DD*DD];
__device__ float g_wkt[DD*DD];
__device__ float g_wvt[DD*DD];
__device__ float g_wot[DD*DD];
__device__ float g_wfct[(size_t)DD*HH];
__device__ float g_wprojt[(size_t)DD*HH];

__device__ __forceinline__ float to_tf32(float x) {
    float r; asm("cvt.rna.tf32.f32 %0, %1;" : "=f"(r) : "f"(x)); return r;
}

__device__ __forceinline__ void mma_tf32(float* c, float a0, float a1, float a2, float a3,
                                         float b0, float b1) {
    asm volatile("mma.sync.aligned.m16n8k8.row.col.f32.tf32.tf32.f32 "
                 "{%0,%1,%2,%3}, {%4,%5,%6,%7}, {%8,%9}, {%0,%1,%2,%3};"
                 : "+f"(c[0]), "+f"(c[1]), "+f"(c[2]), "+f"(c[3])
                 : "r"(__float_as_uint(a0)), "r"(__float_as_uint(a1)),
                   "r"(__float_as_uint(a2)), "r"(__float_as_uint(a3)),
                   "r"(__float_as_uint(b0)), "r"(__float_as_uint(b1)));
}

#define SMEM_STRIDE 20   // 16 K-floats + 4 pad: conflict-free fragment loads

// ---------------- tensor-core (mma.sync tf32) NT GEMM ------------------------
// C[M,N] = epi(alpha * A[M,K] @ B[N,K]^T + ...). Both operands K-major.
// EPI: 0=alpha, 1=+bias, 2=+bias,gelu, 3=+bias,+res
template <int EPI>
__global__ __launch_bounds__(256, 2)
void gemm_mma(const float* __restrict__ A, const float* __restrict__ B,
              const float* __restrict__ bias, const float* __restrict__ res,
              float* __restrict__ C, int N, int K, float alpha,
              size_t sA, size_t sB, size_t sC)
{
    __shared__ float As[128 * SMEM_STRIDE];
    __shared__ float Bs[128 * SMEM_STRIDE];

    A += (size_t)blockIdx.z * sA;
    B += (size_t)blockIdx.z * sB;
    C += (size_t)blockIdx.z * sC;

    int tid = threadIdx.x, lane = tid & 31, wid = tid >> 5;
    int lr = lane >> 2;            // 0..7  (group id)
    int lc = lane & 3;             // 0..3  (thread in group)
    int wm = (wid & 1) * 64;       // warp m-origin in tile (2 warps over m)
    int wn = (wid >> 1) * 32;      // warp n-origin in tile (4 warps over n)
    int m0 = blockIdx.y * 128, n0 = blockIdx.x * 128;

    float acc[4][4][4];
    #pragma unroll
    for (int i = 0; i < 4; i++)
        #pragma unroll
        for (int j = 0; j < 4; j++)
            #pragma unroll
            for (int t = 0; t < 4; t++) acc[i][j][t] = 0.f;

    for (int k0 = 0; k0 < K; k0 += 16) {
        // ---- load 128x16 A and B tiles (K-major), convert to tf32 ----
        #pragma unroll
        for (int i = 0; i < 2; i++) {
            int idx = tid + i * 256;       // 0..511
            int row = idx >> 2;            // 0..127
            int qc  = (idx & 3) * 4;       // 0,4,8,12
            float4 va = *(const float4*)(A + (size_t)(m0 + row) * K + k0 + qc);
            va.x = to_tf32(va.x); va.y = to_tf32(va.y);
            va.z = to_tf32(va.z); va.w = to_tf32(va.w);
            *(float4*)(As + row * SMEM_STRIDE + qc) = va;
            float4 vb = *(const float4*)(B + (size_t)(n0 + row) * K + k0 + qc);
            vb.x = to_tf32(vb.x); vb.y = to_tf32(vb.y);
            vb.z = to_tf32(vb.z); vb.w = to_tf32(vb.w);
            *(float4*)(Bs + row * SMEM_STRIDE + qc) = vb;
        }
        __syncthreads();

        #pragma unroll
        for (int kk = 0; kk < 16; kk += 8) {
            float bf[4][2];
            #pragma unroll
            for (int nf = 0; nf < 4; nf++) {
                int nb = wn + nf * 8 + lr;
                bf[nf][0] = Bs[nb * SMEM_STRIDE + kk + lc];
                bf[nf][1] = Bs[nb * SMEM_STRIDE + kk + lc + 4];
            }
            #pragma unroll
            for (int mf = 0; mf < 4; mf++) {
                int mb = wm + mf * 16;
                float a0 = As[(mb + lr)     * SMEM_STRIDE + kk + lc];
                float a1 = As[(mb + lr + 8) * SMEM_STRIDE + kk + lc];
                float a2 = As[(mb + lr)     * SMEM_STRIDE + kk + lc + 4];
                float a3 = As[(mb + lr + 8) * SMEM_STRIDE + kk + lc + 4];
                #pragma unroll
                for (int nf = 0; nf < 4; nf++)
                    mma_tf32(acc[mf][nf], a0, a1, a2, a3, bf[nf][0], bf[nf][1]);
            }
        }
        __syncthreads();
    }

    // ---- epilogue: each thread owns 2 rows x 2 cols per (mf,nf) fragment ----
    #pragma unroll
    for (int mf = 0; mf < 4; mf++) {
        #pragma unroll
        for (int nf = 0; nf < 4; nf++) {
            int col = n0 + wn + nf * 8 + lc * 2;
            #pragma unroll
            for (int h = 0; h < 2; h++) {
                size_t row = (size_t)(m0 + wm + mf * 16 + lr + h * 8);
                float2 v = make_float2(acc[mf][nf][h * 2], acc[mf][nf][h * 2 + 1]);
                v.x *= alpha; v.y *= alpha;
                if (EPI >= 1) {
                    float2 b2 = *(const float2*)(bias + col);
                    v.x += b2.x; v.y += b2.y;
                }
                if (EPI == 2) {
                    v.x = 0.5f * v.x * (1.f + erff(v.x * 0.70710678118654752f));
                    v.y = 0.5f * v.y * (1.f + erff(v.y * 0.70710678118654752f));
                }
                if (EPI == 3) {
                    float2 r2 = *(const float2*)(res + row * N + col);
                    v.x += r2.x; v.y += r2.y;
                }
                *(float2*)(C + row * N + col) = v;
            }
        }
    }
}

// ---------------- transpose: out[c][r] = in[r][c], batched over z ------------
__global__ void transpose_kernel(const float* __restrict__ in, float* __restrict__ out,
                                 int R, int C) {
    __shared__ float t[32][33];
    size_t zo = (size_t)blockIdx.z * R * C;
    int bx = blockIdx.x * 32, by = blockIdx.y * 32;
    int x = bx + threadIdx.x;
    #pragma unroll
    for (int j = 0; j < 32; j += 8)
        t[threadIdx.y + j][threadIdx.x] = in[zo + (size_t)(by + threadIdx.y + j) * C + x];
    __syncthreads();
    int x2 = by + threadIdx.x;
    #pragma unroll
    for (int j = 0; j < 32; j += 8)
        out[zo + (size_t)(bx + threadIdx.y + j) * R + x2] = t[threadIdx.x][threadIdx.y + j];
}

// ---------------- LayerNorm --------------------------------------------------
__global__ void ln_kernel(const float* __restrict__ x, const float* __restrict__ gw,
                          const float* __restrict__ bw, float* __restrict__ out) {
    size_t base = (size_t)blockIdx.x * DD;
    int tid = threadIdx.x;
    float v0 = x[base+tid], v1 = x[base+tid+256], v2 = x[base+tid+512];
    float s  = v0+v1+v2;
    float sq = v0*v0 + v1*v1 + v2*v2;
    #pragma unroll
    for (int o = 16; o; o >>= 1) {
        s  += __shfl_xor_sync(0xffffffffu, s,  o);
        sq += __shfl_xor_sync(0xffffffffu, sq, o);
    }
    __shared__ float rs[8], rq[8];
    __shared__ float mu_s, rstd_s;
    int w = tid >> 5;
    if ((tid & 31) == 0) { rs[w] = s; rq[w] = sq; }
    __syncthreads();
    if (tid == 0) {
        float a = 0.f, c = 0.f;
        #pragma unroll
        for (int i = 0; i < 8; i++) { a += rs[i]; c += rq[i]; }
        float mu  = a * (1.f/DD);
        float var = c * (1.f/DD) - mu*mu;
        mu_s = mu; rstd_s = rsqrtf(var + 1e-5f);
    }
    __syncthreads();
    float mu = mu_s, rr = rstd_s;
    out[base+tid]     = (v0-mu)*rr*gw[tid]     + bw[tid];
    out[base+tid+256] = (v1-mu)*rr*gw[tid+256] + bw[tid+256];
    out[base+tid+512] = (v2-mu)*rr*gw[tid+512] + bw[tid+512];
}

// ---------------- softmax over last dim (2048) -------------------------------
__global__ void softmax_kernel(float* __restrict__ sc) {
    size_t base = (size_t)blockIdx.x * SS;
    int tid = threadIdx.x;
    float v[8];
    float mx = -1e30f;
    #pragma unroll
    for (int i = 0; i < 8; i++) { v[i] = sc[base + tid + i*256]; mx = fmaxf(mx, v[i]); }
    #pragma unroll
    for (int o = 16; o; o >>= 1) mx = fmaxf(mx, __shfl_xor_sync(0xffffffffu, mx, o));
    __shared__ float rm[8];
    __shared__ float bmax, binv;
    int w = tid >> 5;
    if ((tid & 31) == 0) rm[w] = mx;
    __syncthreads();
    if (tid == 0) {
        float m2 = rm[0];
        #pragma unroll
        for (int i = 1; i < 8; i++) m2 = fmaxf(m2, rm[i]);
        bmax = m2;
    }
    __syncthreads();
    mx = bmax;
    float s = 0.f;
    #pragma unroll
    for (int i = 0; i < 8; i++) { v[i] = expf(v[i] - mx); s += v[i]; }
    #pragma unroll
    for (int o = 16; o; o >>= 1) s += __shfl_xor_sync(0xffffffffu, s, o);
    if ((tid & 31) == 0) rm[w] = s;
    __syncthreads();
    if (tid == 0) {
        float t = 0.f;
        #pragma unroll
        for (int i = 0; i < 8; i++) t += rm[i];
        binv = 1.f / t;
    }
    __syncthreads();
    float inv = binv;
    #pragma unroll
    for (int i = 0; i < 8; i++) sc[base + tid + i*256] = v[i] * inv;
}

// ---------------- host -------------------------------------------------------
static float* sym_addr(const void* s) {
    void* p = nullptr;
    cudaGetSymbolAddress(&p, s);
    return (float*)p;
}

extern "C" void kernel_launch(void* const* d_in, const int* in_sizes, int n_in,
                              void* d_out, int out_size) {
    const float* x     = (const float*)d_in[0];
    const float* ln1_g = (const float*)d_in[1];
    const float* ln1_b = (const float*)d_in[2];
    const float* ln2_g = (const float*)d_in[3];
    const float* ln2_b = (const float*)d_in[4];
    const float* Wq    = (const float*)d_in[5];
    const float* bq    = (const float*)d_in[6];
    const float* Wk    = (const float*)d_in[7];
    const float* bk    = (const float*)d_in[8];
    const float* Wv    = (const float*)d_in[9];
    const float* bv    = (const float*)d_in[10];
    const float* Wo    = (const float*)d_in[11];
    const float* bo    = (const float*)d_in[12];
    const float* Wfc   = (const float*)d_in[13];
    const float* bfc   = (const float*)d_in[14];
    const float* Wproj = (const float*)d_in[15];
    const float* bproj = (const float*)d_in[16];
    float* out = (float*)d_out;

    float* h   = sym_addr(g_h);
    float* q   = sym_addr(g_q);
    float* k   = sym_addr(g_k);
    float* v   = sym_addr(g_v);
    float* vt  = sym_addr(g_vt);
    float* s   = sym_addr(g_s);
    float* y   = sym_addr(g_y);
    float* x1  = sym_addr(g_x1);
    float* h2  = sym_addr(g_h2);
    float* m   = sym_addr(g_m);
    float* wqt = sym_addr(g_wqt);
    float* wkt = sym_addr(g_wkt);
    float* wvt = sym_addr(g_wvt);
    float* wot = sym_addr(g_wot);
    float* wfct   = sym_addr(g_wfct);
    float* wprojt = sym_addr(g_wprojt);

    const float inv_sqrt_d = 1.0f / sqrtf((float)DD);
    dim3 tb(32, 8, 1);

    // weight transposes: W [K,N] -> WT [N,K]  (all GEMMs become NT)
    transpose_kernel<<<dim3(DD/32, DD/32, 1), tb>>>(Wq, wqt, DD, DD);
    transpose_kernel<<<dim3(DD/32, DD/32, 1), tb>>>(Wk, wkt, DD, DD);
    transpose_kernel<<<dim3(DD/32, DD/32, 1), tb>>>(Wv, wvt, DD, DD);
    transpose_kernel<<<dim3(DD/32, DD/32, 1), tb>>>(Wo, wot, DD, DD);
    transpose_kernel<<<dim3(HH/32, DD/32, 1), tb>>>(Wfc, wfct, DD, HH);
    transpose_kernel<<<dim3(DD/32, HH/32, 1), tb>>>(Wproj, wprojt, HH, DD);

    // 1) ln1
    ln_kernel<<<NROWS, 256>>>(x, ln1_g, ln1_b, h);

    // 2) q,k,v = h @ W + b
    dim3 gqkv(DD/128, NROWS/128, 1);
    gemm_mma<1><<<gqkv, 256>>>(h, wqt, bq, nullptr, q, DD, DD, 1.f, 0, 0, 0);
    gemm_mma<1><<<gqkv, 256>>>(h, wkt, bk, nullptr, k, DD, DD, 1.f, 0, 0, 0);
    gemm_mma<1><<<gqkv, 256>>>(h, wvt, bv, nullptr, v, DD, DD, 1.f, 0, 0, 0);

    // transpose v per batch: [S,D] -> [D,S]
    transpose_kernel<<<dim3(DD/32, SS/32, BB), tb>>>(v, vt, SS, DD);

    // 3) scores = q @ k^T / sqrt(D)   (NT: A=q [S,D], B=k [S,D])
    dim3 gsc(SS/128, SS/128, BB);
    gemm_mma<0><<<gsc, 256>>>(q, k, nullptr, nullptr, s, SS, DD, inv_sqrt_d,
                              (size_t)SS*DD, (size_t)SS*DD, (size_t)SS*SS);
    // 4) softmax
    softmax_kernel<<<NROWS, 256>>>(s);

    // 5) y = attn @ v   (NT: A=s [S,S], B=vt [D,S])
    dim3 gav(DD/128, SS/128, BB);
    gemm_mma<0><<<gav, 256>>>(s, vt, nullptr, nullptr, y, DD, SS, 1.f,
                              (size_t)SS*SS, (size_t)DD*SS, (size_t)SS*DD);
    // 6) x1 = x + y @ Wo + bo
    gemm_mma<3><<<gqkv, 256>>>(y, wot, bo, x, x1, DD, DD, 1.f, 0, 0, 0);

    // 7) ln2
    ln_kernel<<<NROWS, 256>>>(x1, ln2_g, ln2_b, h2);

    // 8) m = gelu(h2 @ Wfc + bfc)
    dim3 gfc(HH/128, NROWS/128, 1);
    gemm_mma<2><<<gfc, 256>>>(h2, wfct, bfc, nullptr, m, HH, DD, 1.f, 0, 0, 0);

    // 9) out = x1 + m @ Wproj + bproj
    gemm_mma<3><<<gqkv, 256>>>(m, wprojt, bproj, x1, out, DD, HH, 1.f, 0, 0, 0);
}

// round 15
// speedup vs baseline: 2.8736x; 1.1043x over previous
#include <cuda_runtime.h>
#include <cstdint>
#include <math.h>

#define BB 8
#define SS 2048
#define DD 768
#define HH 3072
#define NROWS (BB*SS)   // 16384

// ---------------- scratch (device globals: no allocations allowed) ----------
__device__ float g_h [NROWS*DD];
__device__ float g_q [NROWS*DD];
__device__ float g_k [NROWS*DD];
__device__ float g_v [NROWS*DD];
__device__ float g_vt[(size_t)BB*DD*SS];
__device__ float g_s [(size_t)BB*SS*SS];
__device__ float g_y [NROWS*DD];
__device__ float g_x1[NROWS*DD];
__device__ float g_h2[NROWS*DD];
__device__ float g_m [(size_t)NROWS*HH];
__device__ float g_wqt[DD*DD];
__device__ float g_wkt[DD*DD];
__device__ float g_wvt[DD*DD];
__device__ float g_wot[DD*DD];
__device__ float g_wfct[(size_t)DD*HH];
__device__ float g_wprojt[(size_t)DD*HH];

__device__ __forceinline__ float to_tf32(float x) {
    float r; asm("cvt.rna.tf32.f32 %0, %1;" : "=f"(r) : "f"(x)); return r;
}

__device__ __forceinline__ void mma_tf32(float* c, float a0, float a1, float a2, float a3,
                                         float b0, float b1) {
    asm volatile("mma.sync.aligned.m16n8k8.row.col.f32.tf32.tf32.f32 "
                 "{%0,%1,%2,%3}, {%4,%5,%6,%7}, {%8,%9}, {%0,%1,%2,%3};"
                 : "+f"(c[0]), "+f"(c[1]), "+f"(c[2]), "+f"(c[3])
                 : "r"(__float_as_uint(a0)), "r"(__float_as_uint(a1)),
                   "r"(__float_as_uint(a2)), "r"(__float_as_uint(a3)),
                   "r"(__float_as_uint(b0)), "r"(__float_as_uint(b1)));
}

#define SMEM_STRIDE 20          // 16 K-floats + 4 pad: conflict-free fragment loads
#define TILE_F (128 * SMEM_STRIDE)

// ---------------- tensor-core (mma.sync tf32) NT GEMM, double-buffered -------
// C[M,N] = epi(alpha * A[M,K] @ B[N,K]^T + ...). Both operands K-major.
// EPI: 0=alpha, 1=+bias, 2=+bias,gelu, 3=+bias,+res
template <int EPI>
__global__ __launch_bounds__(256, 2)
void gemm_mma(const float* __restrict__ A, const float* __restrict__ B,
              const float* __restrict__ bias, const float* __restrict__ res,
              float* __restrict__ C, int N, int K, float alpha,
              size_t sA, size_t sB, size_t sC)
{
    __shared__ float As2[2][TILE_F];
    __shared__ float Bs2[2][TILE_F];

    A += (size_t)blockIdx.z * sA;
    B += (size_t)blockIdx.z * sB;
    C += (size_t)blockIdx.z * sC;

    int tid = threadIdx.x, lane = tid & 31, wid = tid >> 5;
    int lr = lane >> 2;            // 0..7  (group id)
    int lc = lane & 3;             // 0..3  (thread in group)
    int wm = (wid & 1) * 64;       // warp m-origin in tile (2 warps over m)
    int wn = (wid >> 1) * 32;      // warp n-origin in tile (4 warps over n)
    int m0 = blockIdx.y * 128, n0 = blockIdx.x * 128;

    int row = tid >> 2;            // 0..63  (loader row; also row+64)
    int qc  = (tid & 3) * 4;       // 0,4,8,12

    float acc[4][4][4];
    #pragma unroll
    for (int i = 0; i < 4; i++)
        #pragma unroll
        for (int j = 0; j < 4; j++)
            #pragma unroll
            for (int t = 0; t < 4; t++) acc[i][j][t] = 0.f;

    const int nch = K >> 4;        // K-chunks of 16

    float4 pa0, pa1, pb0, pb1;
    // ---- prologue: load chunk 0 ----
    {
        const float* Ab = A + (size_t)(m0 + row) * K + qc;
        const float* Bb = B + (size_t)(n0 + row) * K + qc;
        pa0 = *(const float4*)(Ab);
        pa1 = *(const float4*)(Ab + (size_t)64 * K);
        pb0 = *(const float4*)(Bb);
        pb1 = *(const float4*)(Bb + (size_t)64 * K);
    }

#define STS_TILE(bi) do {                                                     \
        float4 t0 = pa0;                                                      \
        t0.x = to_tf32(t0.x); t0.y = to_tf32(t0.y);                           \
        t0.z = to_tf32(t0.z); t0.w = to_tf32(t0.w);                           \
        *(float4*)(&As2[bi][row * SMEM_STRIDE + qc]) = t0;                    \
        t0 = pa1;                                                             \
        t0.x = to_tf32(t0.x); t0.y = to_tf32(t0.y);                           \
        t0.z = to_tf32(t0.z); t0.w = to_tf32(t0.w);                           \
        *(float4*)(&As2[bi][(row + 64) * SMEM_STRIDE + qc]) = t0;             \
        t0 = pb0;                                                             \
        t0.x = to_tf32(t0.x); t0.y = to_tf32(t0.y);                           \
        t0.z = to_tf32(t0.z); t0.w = to_tf32(t0.w);                           \
        *(float4*)(&Bs2[bi][row * SMEM_STRIDE + qc]) = t0;                    \
        t0 = pb1;                                                             \
        t0.x = to_tf32(t0.x); t0.y = to_tf32(t0.y);                           \
        t0.z = to_tf32(t0.z); t0.w = to_tf32(t0.w);                           \
        *(float4*)(&Bs2[bi][(row + 64) * SMEM_STRIDE + qc]) = t0;             \
    } while (0)

    STS_TILE(0);
    __syncthreads();

    for (int ch = 0; ch < nch; ch++) {
        int cur = ch & 1;
        // ---- prefetch chunk ch+1 from gmem into registers ----
        if (ch + 1 < nch) {
            const float* Ab = A + (size_t)(m0 + row) * K + (ch + 1) * 16 + qc;
            const float* Bb = B + (size_t)(n0 + row) * K + (ch + 1) * 16 + qc;
            pa0 = *(const float4*)(Ab);
            pa1 = *(const float4*)(Ab + (size_t)64 * K);
            pb0 = *(const float4*)(Bb);
            pb1 = *(const float4*)(Bb + (size_t)64 * K);
        }

        // ---- compute chunk ch from buffer cur ----
        const float* As = As2[cur];
        const float* Bs = Bs2[cur];
        #pragma unroll
        for (int kk = 0; kk < 16; kk += 8) {
            float bf[4][2];
            #pragma unroll
            for (int nf = 0; nf < 4; nf++) {
                int nb = wn + nf * 8 + lr;
                bf[nf][0] = Bs[nb * SMEM_STRIDE + kk + lc];
                bf[nf][1] = Bs[nb * SMEM_STRIDE + kk + lc + 4];
            }
            #pragma unroll
            for (int mf = 0; mf < 4; mf++) {
                int mb = wm + mf * 16;
                float a0 = As[(mb + lr)     * SMEM_STRIDE + kk + lc];
                float a1 = As[(mb + lr + 8) * SMEM_STRIDE + kk + lc];
                float a2 = As[(mb + lr)     * SMEM_STRIDE + kk + lc + 4];
                float a3 = As[(mb + lr + 8) * SMEM_STRIDE + kk + lc + 4];
                #pragma unroll
                for (int nf = 0; nf < 4; nf++)
                    mma_tf32(acc[mf][nf], a0, a1, a2, a3, bf[nf][0], bf[nf][1]);
            }
        }

        // ---- stage chunk ch+1 into the other buffer ----
        if (ch + 1 < nch) {
            STS_TILE((ch + 1) & 1);
            __syncthreads();
        }
    }
#undef STS_TILE

    // ---- epilogue: each thread owns 2 rows x 2 cols per (mf,nf) fragment ----
    #pragma unroll
    for (int mf = 0; mf < 4; mf++) {
        #pragma unroll
        for (int nf = 0; nf < 4; nf++) {
            int col = n0 + wn + nf * 8 + lc * 2;
            #pragma unroll
            for (int h = 0; h < 2; h++) {
                size_t rowm = (size_t)(m0 + wm + mf * 16 + lr + h * 8);
                float2 v = make_float2(acc[mf][nf][h * 2], acc[mf][nf][h * 2 + 1]);
                v.x *= alpha; v.y *= alpha;
                if (EPI >= 1) {
                    float2 b2 = *(const float2*)(bias + col);
                    v.x += b2.x; v.y += b2.y;
                }
                if (EPI == 2) {
                    v.x = 0.5f * v.x * (1.f + erff(v.x * 0.70710678118654752f));
                    v.y = 0.5f * v.y * (1.f + erff(v.y * 0.70710678118654752f));
                }
                if (EPI == 3) {
                    float2 r2 = *(const float2*)(res + rowm * N + col);
                    v.x += r2.x; v.y += r2.y;
                }
                *(float2*)(C + rowm * N + col) = v;
            }
        }
    }
}

// ---------------- transpose: out[c][r] = in[r][c], batched over z ------------
__global__ void transpose_kernel(const float* __restrict__ in, float* __restrict__ out,
                                 int R, int C) {
    __shared__ float t[32][33];
    size_t zo = (size_t)blockIdx.z * R * C;
    int bx = blockIdx.x * 32, by = blockIdx.y * 32;
    int x = bx + threadIdx.x;
    #pragma unroll
    for (int j = 0; j < 32; j += 8)
        t[threadIdx.y + j][threadIdx.x] = in[zo + (size_t)(by + threadIdx.y + j) * C + x];
    __syncthreads();
    int x2 = by + threadIdx.x;
    #pragma unroll
    for (int j = 0; j < 32; j += 8)
        out[zo + (size_t)(bx + threadIdx.y + j) * R + x2] = t[threadIdx.x][threadIdx.y + j];
}

// ---------------- LayerNorm --------------------------------------------------
__global__ void ln_kernel(const float* __restrict__ x, const float* __restrict__ gw,
                          const float* __restrict__ bw, float* __restrict__ out) {
    size_t base = (size_t)blockIdx.x * DD;
    int tid = threadIdx.x;
    float v0 = x[base+tid], v1 = x[base+tid+256], v2 = x[base+tid+512];
    float s  = v0+v1+v2;
    float sq = v0*v0 + v1*v1 + v2*v2;
    #pragma unroll
    for (int o = 16; o; o >>= 1) {
        s  += __shfl_xor_sync(0xffffffffu, s,  o);
        sq += __shfl_xor_sync(0xffffffffu, sq, o);
    }
    __shared__ float rs[8], rq[8];
    __shared__ float mu_s, rstd_s;
    int w = tid >> 5;
    if ((tid & 31) == 0) { rs[w] = s; rq[w] = sq; }
    __syncthreads();
    if (tid == 0) {
        float a = 0.f, c = 0.f;
        #pragma unroll
        for (int i = 0; i < 8; i++) { a += rs[i]; c += rq[i]; }
        float mu  = a * (1.f/DD);
        float var = c * (1.f/DD) - mu*mu;
        mu_s = mu; rstd_s = rsqrtf(var + 1e-5f);
    }
    __syncthreads();
    float mu = mu_s, rr = rstd_s;
    out[base+tid]     = (v0-mu)*rr*gw[tid]     + bw[tid];
    out[base+tid+256] = (v1-mu)*rr*gw[tid+256] + bw[tid+256];
    out[base+tid+512] = (v2-mu)*rr*gw[tid+512] + bw[tid+512];
}

// ---------------- softmax over last dim (2048) -------------------------------
__global__ void softmax_kernel(float* __restrict__ sc) {
    size_t base = (size_t)blockIdx.x * SS;
    int tid = threadIdx.x;
    float v[8];
    float mx = -1e30f;
    #pragma unroll
    for (int i = 0; i < 8; i++) { v[i] = sc[base + tid + i*256]; mx = fmaxf(mx, v[i]); }
    #pragma unroll
    for (int o = 16; o; o >>= 1) mx = fmaxf(mx, __shfl_xor_sync(0xffffffffu, mx, o));
    __shared__ float rm[8];
    __shared__ float bmax, binv;
    int w = tid >> 5;
    if ((tid & 31) == 0) rm[w] = mx;
    __syncthreads();
    if (tid == 0) {
        float m2 = rm[0];
        #pragma unroll
        for (int i = 1; i < 8; i++) m2 = fmaxf(m2, rm[i]);
        bmax = m2;
    }
    __syncthreads();
    mx = bmax;
    float s = 0.f;
    #pragma unroll
    for (int i = 0; i < 8; i++) { v[i] = expf(v[i] - mx); s += v[i]; }
    #pragma unroll
    for (int o = 16; o; o >>= 1) s += __shfl_xor_sync(0xffffffffu, s, o);
    if ((tid & 31) == 0) rm[w] = s;
    __syncthreads();
    if (tid == 0) {
        float t = 0.f;
        #pragma unroll
        for (int i = 0; i < 8; i++) t += rm[i];
        binv = 1.f / t;
    }
    __syncthreads();
    float inv = binv;
    #pragma unroll
    for (int i = 0; i < 8; i++) sc[base + tid + i*256] = v[i] * inv;
}

// ---------------- host -------------------------------------------------------
static float* sym_addr(const void* s) {
    void* p = nullptr;
    cudaGetSymbolAddress(&p, s);
    return (float*)p;
}

extern "C" void kernel_launch(void* const* d_in, const int* in_sizes, int n_in,
                              void* d_out, int out_size) {
    const float* x     = (const float*)d_in[0];
    const float* ln1_g = (const float*)d_in[1];
    const float* ln1_b = (const float*)d_in[2];
    const float* ln2_g = (const float*)d_in[3];
    const float* ln2_b = (const float*)d_in[4];
    const float* Wq    = (const float*)d_in[5];
    const float* bq    = (const float*)d_in[6];
    const float* Wk    = (const float*)d_in[7];
    const float* bk    = (const float*)d_in[8];
    const float* Wv    = (const float*)d_in[9];
    const float* bv    = (const float*)d_in[10];
    const float* Wo    = (const float*)d_in[11];
    const float* bo    = (const float*)d_in[12];
    const float* Wfc   = (const float*)d_in[13];
    const float* bfc   = (const float*)d_in[14];
    const float* Wproj = (const float*)d_in[15];
    const float* bproj = (const float*)d_in[16];
    float* out = (float*)d_out;

    float* h   = sym_addr(g_h);
    float* q   = sym_addr(g_q);
    float* k   = sym_addr(g_k);
    float* v   = sym_addr(g_v);
    float* vt  = sym_addr(g_vt);
    float* s   = sym_addr(g_s);
    float* y   = sym_addr(g_y);
    float* x1  = sym_addr(g_x1);
    float* h2  = sym_addr(g_h2);
    float* m   = sym_addr(g_m);
    float* wqt = sym_addr(g_wqt);
    float* wkt = sym_addr(g_wkt);
    float* wvt = sym_addr(g_wvt);
    float* wot = sym_addr(g_wot);
    float* wfct   = sym_addr(g_wfct);
    float* wprojt = sym_addr(g_wprojt);

    const float inv_sqrt_d = 1.0f / sqrtf((float)DD);
    dim3 tb(32, 8, 1);

    // weight transposes: W [K,N] -> WT [N,K]  (all GEMMs become NT)
    transpose_kernel<<<dim3(DD/32, DD/32, 1), tb>>>(Wq, wqt, DD, DD);
    transpose_kernel<<<dim3(DD/32, DD/32, 1), tb>>>(Wk, wkt, DD, DD);
    transpose_kernel<<<dim3(DD/32, DD/32, 1), tb>>>(Wv, wvt, DD, DD);
    transpose_kernel<<<dim3(DD/32, DD/32, 1), tb>>>(Wo, wot, DD, DD);
    transpose_kernel<<<dim3(HH/32, DD/32, 1), tb>>>(Wfc, wfct, DD, HH);
    transpose_kernel<<<dim3(DD/32, HH/32, 1), tb>>>(Wproj, wprojt, HH, DD);

    // 1) ln1
    ln_kernel<<<NROWS, 256>>>(x, ln1_g, ln1_b, h);

    // 2) q,k,v = h @ W + b
    dim3 gqkv(DD/128, NROWS/128, 1);
    gemm_mma<1><<<gqkv, 256>>>(h, wqt, bq, nullptr, q, DD, DD, 1.f, 0, 0, 0);
    gemm_mma<1><<<gqkv, 256>>>(h, wkt, bk, nullptr, k, DD, DD, 1.f, 0, 0, 0);
    gemm_mma<1><<<gqkv, 256>>>(h, wvt, bv, nullptr, v, DD, DD, 1.f, 0, 0, 0);

    // transpose v per batch: [S,D] -> [D,S]
    transpose_kernel<<<dim3(DD/32, SS/32, BB), tb>>>(v, vt, SS, DD);

    // 3) scores = q @ k^T / sqrt(D)   (NT: A=q [S,D], B=k [S,D])
    dim3 gsc(SS/128, SS/128, BB);
    gemm_mma<0><<<gsc, 256>>>(q, k, nullptr, nullptr, s, SS, DD, inv_sqrt_d,
                              (size_t)SS*DD, (size_t)SS*DD, (size_t)SS*SS);
    // 4) softmax
    softmax_kernel<<<NROWS, 256>>>(s);

    // 5) y = attn @ v   (NT: A=s [S,S], B=vt [D,S])
    dim3 gav(DD/128, SS/128, BB);
    gemm_mma<0><<<gav, 256>>>(s, vt, nullptr, nullptr, y, DD, SS, 1.f,
                              (size_t)SS*SS, (size_t)DD*SS, (size_t)SS*DD);
    // 6) x1 = x + y @ Wo + bo
    gemm_mma<3><<<gqkv, 256>>>(y, wot, bo, x, x1, DD, DD, 1.f, 0, 0, 0);

    // 7) ln2
    ln_kernel<<<NROWS, 256>>>(x1, ln2_g, ln2_b, h2);

    // 8) m = gelu(h2 @ Wfc + bfc)
    dim3 gfc(HH/32 == 0 ? 1 : HH/128, NROWS/128, 1);
    gemm_mma<2><<<dim3(HH/128, NROWS/128, 1), 256>>>(h2, wfct, bfc, nullptr, m, HH, DD, 1.f, 0, 0, 0);

    // 9) out = x1 + m @ Wproj + bproj
    gemm_mma<3><<<gqkv, 256>>>(m, wprojt, bproj, x1, out, DD, HH, 1.f, 0, 0, 0);
}